// round 16
// baseline (speedup 1.0000x reference)
#include <cuda_runtime.h>
#include <cuda_fp16.h>
#include <cstdint>

#define BB 16
#define DD 2048
#define LL 512
#define NN 8192
#define NPAIR 32         // pair i = (u_l ch i, u_h ch i) sharing B ch i
#define TCHUNK 64
#define WARMUP 8

// Scratch (__device__ globals; allocation-free rule)
__device__ __half g_Ph[(size_t)NN * DD];          // 32 MB  P[n][m] fp16 (+bias)
__device__ __half g_Ah[(size_t)NN * 2 * DD];      // 64 MB  [u_l | u_h] per row
__device__ __half g_Bh[(size_t)DD * DD];          //  8 MB  w_h [m][k]

// ---------------------------------------------------------------------------
// Portable PTX helpers (sm_80-level ISA; ptxas target is sm_103 base)
// ---------------------------------------------------------------------------
__device__ __forceinline__ uint32_t s2u(const void* p) {
    return (uint32_t)__cvta_generic_to_shared(const_cast<void*>(p));
}
__device__ __forceinline__ void cp16(uint32_t dst, const void* src) {
    asm volatile("cp.async.cg.shared.global [%0], [%1], 16;" :: "r"(dst), "l"(src));
}
#define CP_COMMIT() asm volatile("cp.async.commit_group;" ::: "memory")
#define CP_WAIT0()  asm volatile("cp.async.wait_group 0;" ::: "memory")

__device__ __forceinline__ void ldsm4(uint32_t* r, uint32_t addr) {
    asm volatile("ldmatrix.sync.aligned.m8n8.x4.shared.b16 {%0,%1,%2,%3}, [%4];"
                 : "=r"(r[0]), "=r"(r[1]), "=r"(r[2]), "=r"(r[3]) : "r"(addr));
}
__device__ __forceinline__ void mma_f16(float* c, const uint32_t* a,
                                        uint32_t b0, uint32_t b1) {
    asm volatile(
        "mma.sync.aligned.m16n8k16.row.col.f32.f16.f16.f32 "
        "{%0,%1,%2,%3}, {%4,%5,%6,%7}, {%8,%9}, {%0,%1,%2,%3};"
        : "+f"(c[0]), "+f"(c[1]), "+f"(c[2]), "+f"(c[3])
        : "r"(a[0]), "r"(a[1]), "r"(a[2]), "r"(a[3]), "r"(b0), "r"(b1));
}

// ---------------------------------------------------------------------------
// conv_w: w -> fp16
// ---------------------------------------------------------------------------
__global__ void conv_w_kernel(const float* __restrict__ w, __half* __restrict__ Bh) {
    const size_t i = (size_t)blockIdx.x * 256 + threadIdx.x;
    Bh[i] = __float2half_rn(w[i]);
}

// ---------------------------------------------------------------------------
// conv_u: transpose u[b][h][t] -> A row n=b*L+t: [u_l(h) | u_h(h)]
// ---------------------------------------------------------------------------
__global__ void conv_u_kernel(const float* __restrict__ u, __half* __restrict__ Ah) {
    __shared__ float tile[32][33];
    const int b = blockIdx.z;
    const int t0 = blockIdx.x * 32, h0 = blockIdx.y * 32;
    const int tx = threadIdx.x, ty = threadIdx.y;
    const float* up = u + ((size_t)b * DD + h0) * LL + t0;
#pragma unroll
    for (int j = 0; j < 32; j += 8)
        tile[ty + j][tx] = up[(size_t)(ty + j) * LL + tx];   // [h_loc][t_loc]
    __syncthreads();
#pragma unroll
    for (int j = 0; j < 32; j += 8) {
        float v = tile[tx][ty + j];                // h = h0+tx, t = t0+ty+j
        __half hi = __float2half_rn(v);
        __half lo = __float2half_rn(v - __half2float(hi));
        __half* row = Ah + ((size_t)b * LL + t0 + ty + j) * 2 * DD;
        row[h0 + tx]      = lo;                    // u_l half
        row[DD + h0 + tx] = hi;                    // u_h half
    }
}

// ---------------------------------------------------------------------------
// Pair-fused fp16 HMMA GEMM, 4-stage / 16-barrier superiterations:
//   P = u_l.w_h + u_h.w_h + bias, f32 accumulate.
// Stage = [B 16K | A_ul 16K | A_uh 16K] = 48KB; 4 stages (192KB) -> 1 CTA/SM.
// Each superiteration: ONE wait+barrier, loads 2 pairs, computes 2 pairs
// (256 HMMA/warp between barriers; 16 independent accum chains for ILP).
// CTA 128n x 128m, 8 warps (2n x 4m), warp tile 64x32.
// ---------------------------------------------------------------------------
#define STB 49152
#define SMEMG (4 * STB)           // 192 KB

__global__ __launch_bounds__(256, 1)
void gemm_kernel(const __half* __restrict__ A, const __half* __restrict__ Bm,
                 const float* __restrict__ bias, __half* __restrict__ P) {
    extern __shared__ char smem[];
    const uint32_t s0 = s2u(smem);
    const int tid = threadIdx.x;
    const int wid = tid >> 5, lane = tid & 31;
    const int wn = wid & 1, wm = wid >> 1;      // warps: 2n x 4m
    const int m0 = blockIdx.x * 128;
    const int n0 = blockIdx.y * 128;

    const char* Ab = (const char*)(A  + (size_t)n0 * 2 * DD);   // row stride 8192 B
    const char* Bb = (const char*)(Bm + (size_t)m0 * DD);       // row stride 4096 B

    // Precomputed per-thread cp.async addressing
    const char* pA[4]; const char* pB[4];
    uint32_t soff[4];
#pragma unroll
    for (int i = 0; i < 4; ++i) {
        int idx = tid + i * 256;
        int r = idx >> 3, c = idx & 7;
        uint32_t off = (uint32_t)r * 128u + (uint32_t)c * 16u;
        soff[i] = off ^ ((off >> 3) & 0x70);
        pA[i] = Ab + (size_t)r * 8192 + c * 16;
        pB[i] = Bb + (size_t)r * 4096 + c * 16;
    }

    auto load_pair = [&](int stage, int pr) {
        const uint32_t sa = s0 + stage * STB;
        const int k = pr << 7;                 // 128 B per chunk
#pragma unroll
        for (int i = 0; i < 4; ++i) cp16(sa + soff[i],          pB[i] + k);         // B
#pragma unroll
        for (int i = 0; i < 4; ++i) cp16(sa + 16384u + soff[i], pA[i] + k);         // A u_l
#pragma unroll
        for (int i = 0; i < 4; ++i) cp16(sa + 32768u + soff[i], pA[i] + k + 4096);  // A u_h
    };

    load_pair(0, 0);
    load_pair(1, 1);
    CP_COMMIT();

    // ldmatrix lane addressing (B at stage+0; A_ul at +16384; A_uh at +32768)
    uint32_t a_rbase[4], a_xm[4];
#pragma unroll
    for (int ni = 0; ni < 4; ++ni) {
        uint32_t row = wn * 64 + ni * 16 + (lane & 15);
        a_rbase[ni] = 16384u + row * 128u;
        a_xm[ni] = (row & 7) << 4;
    }
    const uint32_t a_koff = (lane >> 4) * 16;
    uint32_t b_rbase[2], b_xm[2];
    {
        uint32_t mrow_in16 = (lane & 7) + ((lane >> 4) << 3);
#pragma unroll
        for (int bi = 0; bi < 2; ++bi) {
            uint32_t row = wm * 32 + bi * 16 + mrow_in16;
            b_rbase[bi] = row * 128u;
            b_xm[bi] = (row & 7) << 4;
        }
    }
    const uint32_t b_koff = ((lane >> 3) & 1) * 16;

    float c[4][4][4];
#pragma unroll
    for (int i = 0; i < 4; ++i)
#pragma unroll
        for (int j = 0; j < 4; ++j)
#pragma unroll
            for (int v = 0; v < 4; ++v) c[i][j][v] = 0.f;

    auto compute_pair = [&](int stage) {
        const uint32_t sa = s0 + stage * STB;
#pragma unroll
        for (int ks = 0; ks < 4; ++ks) {
            uint32_t b[2][4], a[4][4];
#pragma unroll
            for (int bi = 0; bi < 2; ++bi)
                ldsm4(b[bi], sa + b_rbase[bi] + ((ks * 32 + b_koff) ^ b_xm[bi]));
            // u_l half
#pragma unroll
            for (int ni = 0; ni < 4; ++ni)
                ldsm4(a[ni], sa + a_rbase[ni] + ((ks * 32 + a_koff) ^ a_xm[ni]));
#pragma unroll
            for (int ni = 0; ni < 4; ++ni)
#pragma unroll
                for (int bi = 0; bi < 2; ++bi) {
                    mma_f16(c[ni][bi * 2],     a[ni], b[bi][0], b[bi][1]);
                    mma_f16(c[ni][bi * 2 + 1], a[ni], b[bi][2], b[bi][3]);
                }
            // u_h half (same B fragments)
#pragma unroll
            for (int ni = 0; ni < 4; ++ni)
                ldsm4(a[ni], sa + a_rbase[ni] + 16384u + ((ks * 32 + a_koff) ^ a_xm[ni]));
#pragma unroll
            for (int ni = 0; ni < 4; ++ni)
#pragma unroll
                for (int bi = 0; bi < 2; ++bi) {
                    mma_f16(c[ni][bi * 2],     a[ni], b[bi][0], b[bi][1]);
                    mma_f16(c[ni][bi * 2 + 1], a[ni], b[bi][2], b[bi][3]);
                }
        }
    };

    for (int si = 0; si < NPAIR / 2; ++si) {
        const int p0 = 2 * si;
        CP_WAIT0();                 // all issued loads (pairs <= p0+1) complete
        __syncthreads();            // visible to all; stages (p0+2)&3,(p0+3)&3 free
        if (p0 + 2 < NPAIR) {
            load_pair((p0 + 2) & 3, p0 + 2);
            load_pair((p0 + 3) & 3, p0 + 3);
            CP_COMMIT();
        }
        compute_pair(p0 & 3);
        compute_pair((p0 + 1) & 3);
    }

    // Epilogue: add bias[m], convert to fp16, store half2
    const int q = lane >> 2, qr = lane & 3;
    float2 bv[4];
#pragma unroll
    for (int mi = 0; mi < 4; ++mi)
        bv[mi] = *(const float2*)(bias + m0 + wm * 32 + mi * 8 + qr * 2);
#pragma unroll
    for (int ni = 0; ni < 4; ++ni) {
        int row = n0 + wn * 64 + ni * 16 + q;
#pragma unroll
        for (int mi = 0; mi < 4; ++mi) {
            int col = m0 + wm * 32 + mi * 8 + qr * 2;
            *(__half2*)(P + (size_t)row * DD + col) =
                __halves2half2(__float2half_rn(c[ni][mi][0] + bv[mi].x),
                               __float2half_rn(c[ni][mi][1] + bv[mi].y));
            *(__half2*)(P + (size_t)(row + 8) * DD + col) =
                __halves2half2(__float2half_rn(c[ni][mi][2] + bv[mi].x),
                               __float2half_rn(c[ni][mi][3] + bv[mi].y));
        }
    }
}

// ---------------------------------------------------------------------------
// Scan, t-chunked with fading-memory warmup; float4 output stores.
// ---------------------------------------------------------------------------
__device__ __forceinline__ float tanh_fast(float x) {
    float r;
    asm("tanh.approx.f32 %0, %1;" : "=f"(r) : "f"(x));
    return r;
}

__global__ __launch_bounds__(128)
void scan_kernel(const float* __restrict__ whh,
                 const __half* __restrict__ P, float* __restrict__ out) {
    __shared__ float tile[128][33];
    const int b = blockIdx.y;
    const int p0 = blockIdx.x * 128;
    const int ts = blockIdx.z * TCHUNK;
    const int tid = threadIdx.x;
    const int p = p0 + tid;
    const int lane = tid & 31, wrp = tid >> 5;
    const float d = whh[(size_t)p * DD + p];
    const __half* Pb = P + (size_t)b * LL * DD + p;

    float x = 0.f;
    if (ts > 0) {
        float wv[WARMUP];
#pragma unroll
        for (int i = 0; i < WARMUP; ++i)
            wv[i] = __half2float(Pb[(size_t)(ts - WARMUP + i) * DD]);
#pragma unroll
        for (int i = 0; i < WARMUP; ++i)
            x = tanh_fast(fmaf(d, x, wv[i]));
    }

    for (int t0 = ts; t0 < ts + TCHUNK; t0 += 32) {
        float pv[32];
#pragma unroll
        for (int tt = 0; tt < 32; ++tt)
            pv[tt] = __half2float(Pb[(size_t)(t0 + tt) * DD]);
#pragma unroll
        for (int tt = 0; tt < 32; ++tt) {
            x = tanh_fast(fmaf(d, x, pv[tt]));
            tile[tid][tt] = x;
        }
        __syncthreads();
        const int rsub = lane >> 3, tq = (lane & 7) * 4;
#pragma unroll
        for (int pp = 0; pp < 8; ++pp) {
            int pl = wrp * 32 + pp * 4 + rsub;
            float4 v = make_float4(tile[pl][tq], tile[pl][tq + 1],
                                   tile[pl][tq + 2], tile[pl][tq + 3]);
            *(float4*)(out + ((size_t)b * DD + p0 + pl) * LL + t0 + tq) = v;
        }
        __syncthreads();
    }
}

// ---------------------------------------------------------------------------
extern "C" void kernel_launch(void* const* d_in, const int* in_sizes, int n_in,
                              void* d_out, int out_size) {
    const float* u    = (const float*)d_in[0];
    const float* w_in = (const float*)d_in[1];
    const float* w_hh = (const float*)d_in[2];
    const float* bias = (const float*)d_in[3];
    float* out = (float*)d_out;

    __half* P;  cudaGetSymbolAddress((void**)&P,  g_Ph);
    __half* Ah; cudaGetSymbolAddress((void**)&Ah, g_Ah);
    __half* Bh; cudaGetSymbolAddress((void**)&Bh, g_Bh);

    conv_w_kernel<<<(DD * DD) / 256, 256>>>(w_in, Bh);
    conv_u_kernel<<<dim3(LL / 32, DD / 32, BB), dim3(32, 8)>>>(u, Ah);

    cudaFuncSetAttribute(gemm_kernel, cudaFuncAttributeMaxDynamicSharedMemorySize, SMEMG);
    gemm_kernel<<<dim3(DD / 128, NN / 128), 256, SMEMG>>>(Ah, Bh, bias, P);

    scan_kernel<<<dim3(DD / 128, BB, LL / TCHUNK), 128>>>(w_hh, P, out);
}

// round 17
// speedup vs baseline: 1.1179x; 1.1179x over previous
#include <cuda_runtime.h>
#include <cuda_fp16.h>
#include <cstdint>

#define BB 16
#define DD 2048
#define LL 512
#define NN 8192
#define NPAIR 32         // pair i = (u_l ch i, u_h ch i) sharing B ch i
#define TCHUNK 64
#define WARMUP 8

// Scratch (__device__ globals; allocation-free rule)
__device__ __half g_Ph[(size_t)NN * DD];          // 32 MB  P[n][m] fp16 (+bias)
__device__ __half g_Ah[(size_t)NN * 2 * DD];      // 64 MB  [u_l | u_h] per row
__device__ __half g_Bh[(size_t)DD * DD];          //  8 MB  w_h [m][k]

// ---------------------------------------------------------------------------
// Portable PTX helpers (sm_80-level ISA; ptxas target is sm_103 base)
// ---------------------------------------------------------------------------
__device__ __forceinline__ uint32_t s2u(const void* p) {
    return (uint32_t)__cvta_generic_to_shared(const_cast<void*>(p));
}
__device__ __forceinline__ void cp16(uint32_t dst, const void* src) {
    asm volatile("cp.async.cg.shared.global [%0], [%1], 16;" :: "r"(dst), "l"(src));
}
#define CP_COMMIT() asm volatile("cp.async.commit_group;" ::: "memory")
#define CP_WAIT0()  asm volatile("cp.async.wait_group 0;" ::: "memory")

__device__ __forceinline__ void ldsm4(uint32_t* r, uint32_t addr) {
    asm volatile("ldmatrix.sync.aligned.m8n8.x4.shared.b16 {%0,%1,%2,%3}, [%4];"
                 : "=r"(r[0]), "=r"(r[1]), "=r"(r[2]), "=r"(r[3]) : "r"(addr));
}
__device__ __forceinline__ void mma_f16(float* c, const uint32_t* a,
                                        uint32_t b0, uint32_t b1) {
    asm volatile(
        "mma.sync.aligned.m16n8k16.row.col.f32.f16.f16.f32 "
        "{%0,%1,%2,%3}, {%4,%5,%6,%7}, {%8,%9}, {%0,%1,%2,%3};"
        : "+f"(c[0]), "+f"(c[1]), "+f"(c[2]), "+f"(c[3])
        : "r"(a[0]), "r"(a[1]), "r"(a[2]), "r"(a[3]), "r"(b0), "r"(b1));
}

// ---------------------------------------------------------------------------
// conv_w: w -> fp16, float2 -> half2 (128B warp segments)
// ---------------------------------------------------------------------------
__global__ void conv_w_kernel(const float* __restrict__ w, __half* __restrict__ Bh) {
    const size_t i = ((size_t)blockIdx.x * 256 + threadIdx.x) * 2;
    float2 v = *(const float2*)(w + i);
    *(__half2*)(Bh + i) = __halves2half2(__float2half_rn(v.x), __float2half_rn(v.y));
}

// ---------------------------------------------------------------------------
// conv_u: transpose u[b][h][t] -> A row n=b*L+t: [u_l(h) | u_h(h)]
// 64h x 32t tile; half2 writes (128B warp segments).
// ---------------------------------------------------------------------------
__global__ void conv_u_kernel(const float* __restrict__ u, __half* __restrict__ Ah) {
    __shared__ float tile[64][33];
    const int b = blockIdx.z;
    const int t0 = blockIdx.x * 32, h0 = blockIdx.y * 64;
    const int tx = threadIdx.x, ty = threadIdx.y;     // block (32, 8)
    const int tid = ty * 32 + tx;
    const float* up = u + ((size_t)b * DD + h0) * LL + t0;
#pragma unroll
    for (int hh = 0; hh < 64; hh += 8)
        tile[hh + ty][tx] = up[(size_t)(hh + ty) * LL + tx];   // [h_loc][t_loc]
    __syncthreads();

    const int wr_t = tid >> 5;            // 0..7
    const int wr_h = (tid & 31) * 2;      // 0..62, even
#pragma unroll
    for (int jt = 0; jt < 32; jt += 8) {
        int tl = jt + wr_t;
        float v0 = tile[wr_h][tl];
        float v1 = tile[wr_h + 1][tl];
        __half h0a = __float2half_rn(v0);
        __half h1a = __float2half_rn(v1);
        __half l0 = __float2half_rn(v0 - __half2float(h0a));
        __half l1 = __float2half_rn(v1 - __half2float(h1a));
        __half* row = Ah + ((size_t)b * LL + t0 + tl) * 2 * DD;
        *(__half2*)(row + h0 + wr_h)      = __halves2half2(l0, l1);   // u_l half
        *(__half2*)(row + DD + h0 + wr_h) = __halves2half2(h0a, h1a); // u_h half
    }
}

// ---------------------------------------------------------------------------
// Pair-fused fp16 HMMA GEMM (R15 champion config, verbatim):
//   P = u_l.w_h + u_h.w_h + bias, f32 accumulate.
// Stage = [B 16K | A_ul 16K | A_uh 16K] = 48KB; 2 stages (96KB) -> 2 CTAs/SM.
// CTA 128n x 128m, 8 warps (2n x 4m), warp tile 64x32. One sync per pair (32).
// ---------------------------------------------------------------------------
#define STB 49152
#define SMEMG (2 * STB)

__global__ __launch_bounds__(256, 2)
void gemm_kernel(const __half* __restrict__ A, const __half* __restrict__ Bm,
                 const float* __restrict__ bias, __half* __restrict__ P) {
    extern __shared__ char smem[];
    const uint32_t s0 = s2u(smem);
    const int tid = threadIdx.x;
    const int wid = tid >> 5, lane = tid & 31;
    const int wn = wid & 1, wm = wid >> 1;      // warps: 2n x 4m
    const int m0 = blockIdx.x * 128;
    const int n0 = blockIdx.y * 128;

    const char* Ab = (const char*)(A  + (size_t)n0 * 2 * DD);   // row stride 8192 B
    const char* Bb = (const char*)(Bm + (size_t)m0 * DD);       // row stride 4096 B

    // Precomputed per-thread cp.async addressing
    const char* pA[4]; const char* pB[4];
    uint32_t soff[4];
#pragma unroll
    for (int i = 0; i < 4; ++i) {
        int idx = tid + i * 256;
        int r = idx >> 3, c = idx & 7;
        uint32_t off = (uint32_t)r * 128u + (uint32_t)c * 16u;
        soff[i] = off ^ ((off >> 3) & 0x70);
        pA[i] = Ab + (size_t)r * 8192 + c * 16;
        pB[i] = Bb + (size_t)r * 4096 + c * 16;
    }

    auto load_pair = [&](int stage, int pr) {
        const uint32_t sa = s0 + stage * STB;
        const int k = pr << 7;                 // 128 B per chunk
#pragma unroll
        for (int i = 0; i < 4; ++i) cp16(sa + soff[i],          pB[i] + k);         // B
#pragma unroll
        for (int i = 0; i < 4; ++i) cp16(sa + 16384u + soff[i], pA[i] + k);         // A u_l
#pragma unroll
        for (int i = 0; i < 4; ++i) cp16(sa + 32768u + soff[i], pA[i] + k + 4096);  // A u_h
    };

    load_pair(0, 0); CP_COMMIT();

    // ldmatrix lane addressing (B at stage+0; A_ul at +16384; A_uh at +32768)
    uint32_t a_rbase[4], a_xm[4];
#pragma unroll
    for (int ni = 0; ni < 4; ++ni) {
        uint32_t row = wn * 64 + ni * 16 + (lane & 15);
        a_rbase[ni] = 16384u + row * 128u;
        a_xm[ni] = (row & 7) << 4;
    }
    const uint32_t a_koff = (lane >> 4) * 16;
    uint32_t b_rbase[2], b_xm[2];
    {
        uint32_t mrow_in16 = (lane & 7) + ((lane >> 4) << 3);
#pragma unroll
        for (int bi = 0; bi < 2; ++bi) {
            uint32_t row = wm * 32 + bi * 16 + mrow_in16;
            b_rbase[bi] = row * 128u;
            b_xm[bi] = (row & 7) << 4;
        }
    }
    const uint32_t b_koff = ((lane >> 3) & 1) * 16;

    float c[4][4][4];
#pragma unroll
    for (int i = 0; i < 4; ++i)
#pragma unroll
        for (int j = 0; j < 4; ++j)
#pragma unroll
            for (int v = 0; v < 4; ++v) c[i][j][v] = 0.f;

    for (int pr = 0; pr < NPAIR; ++pr) {
        CP_WAIT0();                 // this pair's loads done (issued last iter)
        __syncthreads();            // all threads' loads visible; stage free
        if (pr + 1 < NPAIR) { load_pair((pr + 1) & 1, pr + 1); CP_COMMIT(); }

        const uint32_t sa = s0 + (pr & 1) * STB;
#pragma unroll
        for (int ks = 0; ks < 4; ++ks) {
            uint32_t b[2][4], a[4][4];
#pragma unroll
            for (int bi = 0; bi < 2; ++bi)
                ldsm4(b[bi], sa + b_rbase[bi] + ((ks * 32 + b_koff) ^ b_xm[bi]));
            // u_l half
#pragma unroll
            for (int ni = 0; ni < 4; ++ni)
                ldsm4(a[ni], sa + a_rbase[ni] + ((ks * 32 + a_koff) ^ a_xm[ni]));
#pragma unroll
            for (int ni = 0; ni < 4; ++ni)
#pragma unroll
                for (int bi = 0; bi < 2; ++bi) {
                    mma_f16(c[ni][bi * 2],     a[ni], b[bi][0], b[bi][1]);
                    mma_f16(c[ni][bi * 2 + 1], a[ni], b[bi][2], b[bi][3]);
                }
            // u_h half (same B fragments)
#pragma unroll
            for (int ni = 0; ni < 4; ++ni)
                ldsm4(a[ni], sa + a_rbase[ni] + 16384u + ((ks * 32 + a_koff) ^ a_xm[ni]));
#pragma unroll
            for (int ni = 0; ni < 4; ++ni)
#pragma unroll
                for (int bi = 0; bi < 2; ++bi) {
                    mma_f16(c[ni][bi * 2],     a[ni], b[bi][0], b[bi][1]);
                    mma_f16(c[ni][bi * 2 + 1], a[ni], b[bi][2], b[bi][3]);
                }
        }
    }

    // Epilogue: add bias[m], convert to fp16, store half2
    const int q = lane >> 2, qr = lane & 3;
    float2 bv[4];
#pragma unroll
    for (int mi = 0; mi < 4; ++mi)
        bv[mi] = *(const float2*)(bias + m0 + wm * 32 + mi * 8 + qr * 2);
#pragma unroll
    for (int ni = 0; ni < 4; ++ni) {
        int row = n0 + wn * 64 + ni * 16 + q;
#pragma unroll
        for (int mi = 0; mi < 4; ++mi) {
            int col = m0 + wm * 32 + mi * 8 + qr * 2;
            *(__half2*)(P + (size_t)row * DD + col) =
                __halves2half2(__float2half_rn(c[ni][mi][0] + bv[mi].x),
                               __float2half_rn(c[ni][mi][1] + bv[mi].y));
            *(__half2*)(P + (size_t)(row + 8) * DD + col) =
                __halves2half2(__float2half_rn(c[ni][mi][2] + bv[mi].x),
                               __float2half_rn(c[ni][mi][3] + bv[mi].y));
        }
    }
}

// ---------------------------------------------------------------------------
// Scan, t-chunked with fading-memory warmup; float4 output stores (R15 verbatim).
// ---------------------------------------------------------------------------
__device__ __forceinline__ float tanh_fast(float x) {
    float r;
    asm("tanh.approx.f32 %0, %1;" : "=f"(r) : "f"(x));
    return r;
}

__global__ __launch_bounds__(128)
void scan_kernel(const float* __restrict__ whh,
                 const __half* __restrict__ P, float* __restrict__ out) {
    __shared__ float tile[128][33];
    const int b = blockIdx.y;
    const int p0 = blockIdx.x * 128;
    const int ts = blockIdx.z * TCHUNK;
    const int tid = threadIdx.x;
    const int p = p0 + tid;
    const int lane = tid & 31, wrp = tid >> 5;
    const float d = whh[(size_t)p * DD + p];
    const __half* Pb = P + (size_t)b * LL * DD + p;

    float x = 0.f;
    if (ts > 0) {
        float wv[WARMUP];
#pragma unroll
        for (int i = 0; i < WARMUP; ++i)
            wv[i] = __half2float(Pb[(size_t)(ts - WARMUP + i) * DD]);
#pragma unroll
        for (int i = 0; i < WARMUP; ++i)
            x = tanh_fast(fmaf(d, x, wv[i]));
    }

    for (int t0 = ts; t0 < ts + TCHUNK; t0 += 32) {
        float pv[32];
#pragma unroll
        for (int tt = 0; tt < 32; ++tt)
            pv[tt] = __half2float(Pb[(size_t)(t0 + tt) * DD]);
#pragma unroll
        for (int tt = 0; tt < 32; ++tt) {
            x = tanh_fast(fmaf(d, x, pv[tt]));
            tile[tid][tt] = x;
        }
        __syncthreads();
        const int rsub = lane >> 3, tq = (lane & 7) * 4;
#pragma unroll
        for (int pp = 0; pp < 8; ++pp) {
            int pl = wrp * 32 + pp * 4 + rsub;
            float4 v = make_float4(tile[pl][tq], tile[pl][tq + 1],
                                   tile[pl][tq + 2], tile[pl][tq + 3]);
            *(float4*)(out + ((size_t)b * DD + p0 + pl) * LL + t0 + tq) = v;
        }
        __syncthreads();
    }
}

// ---------------------------------------------------------------------------
extern "C" void kernel_launch(void* const* d_in, const int* in_sizes, int n_in,
                              void* d_out, int out_size) {
    const float* u    = (const float*)d_in[0];
    const float* w_in = (const float*)d_in[1];
    const float* w_hh = (const float*)d_in[2];
    const float* bias = (const float*)d_in[3];
    float* out = (float*)d_out;

    __half* P;  cudaGetSymbolAddress((void**)&P,  g_Ph);
    __half* Ah; cudaGetSymbolAddress((void**)&Ah, g_Ah);
    __half* Bh; cudaGetSymbolAddress((void**)&Bh, g_Bh);

    conv_w_kernel<<<(DD * DD) / 512, 256>>>(w_in, Bh);
    conv_u_kernel<<<dim3(LL / 32, DD / 64, BB), dim3(32, 8)>>>(u, Ah);

    cudaFuncSetAttribute(gemm_kernel, cudaFuncAttributeMaxDynamicSharedMemorySize, SMEMG);
    gemm_kernel<<<dim3(DD / 128, NN / 128), 256, SMEMG>>>(Ah, Bh, bias, P);

    scan_kernel<<<dim3(DD / 128, BB, LL / TCHUNK), 128>>>(w_hh, P, out);
}